// round 17
// baseline (speedup 1.0000x reference)
#include <cuda_runtime.h>
#include <cstdint>
#include <math.h>

// Problem constants
#define H_HEADS 16
#define BATCH   2
#define L       1024
#define D       64
#define USAMP   7097
#define USEL    34
#define DMODEL  (H_HEADS * D)   // 1024
#define MROWS   (BATCH * L)     // 2048

// PV tiling
#define NCH 32
#define CHK 32

// ---------------- scratch (static device globals; no allocation) ----------------
__device__ float g_S[BATCH][L][L];
__device__ uint8_t g_cnt8[BATCH][L][16];
__device__ float g_M[BATCH][H_HEADS][L];
__device__ int   g_top[BATCH][H_HEADS][USEL];
__device__ int   g_sel[BATCH][H_HEADS][L];
__device__ float g_meanv[BATCH][D];
__device__ float g_pacc[BATCH][H_HEADS][USEL][NCH][64];
__device__ float g_psum[BATCH][H_HEADS][USEL][NCH];
__device__ float g_delta[BATCH][H_HEADS][USEL][D];
__device__ float g_E[BATCH][H_HEADS][USEL][DMODEL];
__device__ float g_base[BATCH][DMODEL];
__device__ float g_basep[4][BATCH][DMODEL];

// ---------------- f32x2 packed-FMA helpers (sm_103a FFMA2 via PTX) ----------------
__device__ __forceinline__ unsigned long long bcast2(float x) {
    unsigned long long r;
    asm("mov.b64 %0, {%1, %1};" : "=l"(r) : "f"(x));
    return r;
}
__device__ __forceinline__ void ffma2(unsigned long long& d,
                                      unsigned long long a, unsigned long long b) {
    asm("fma.rn.f32x2 %0, %1, %2, %0;" : "+l"(d) : "l"(a), "l"(b));
}
__device__ __forceinline__ float2 unpack2(unsigned long long p) {
    float2 f;
    asm("mov.b64 {%0, %1}, %2;" : "=f"(f.x), "=f"(f.y) : "l"(p));
    return f;
}

// ---------------- threefry2x32 (JAX-compatible) ----------------
__device__ __forceinline__ uint32_t rotl32(uint32_t x, int d) {
    return (x << d) | (x >> (32 - d));
}

__device__ __forceinline__ void threefry2x32(uint32_t k0, uint32_t k1,
                                             uint32_t x0, uint32_t x1,
                                             uint32_t& o0, uint32_t& o1) {
    uint32_t ks2 = k0 ^ k1 ^ 0x1BD11BDAu;
    x0 += k0; x1 += k1;
#define TFR(r) { x0 += x1; x1 = rotl32(x1, (r)); x1 ^= x0; }
    TFR(13) TFR(15) TFR(26) TFR(6)   x0 += k1;  x1 += ks2 + 1u;
    TFR(17) TFR(29) TFR(16) TFR(24)  x0 += ks2; x1 += k0 + 2u;
    TFR(13) TFR(15) TFR(26) TFR(6)   x0 += k0;  x1 += k1 + 3u;
    TFR(17) TFR(29) TFR(16) TFR(24)  x0 += k1;  x1 += ks2 + 4u;
    TFR(13) TFR(15) TFR(26) TFR(6)   x0 += ks2; x1 += k0 + 5u;
#undef TFR
    o0 = x0; o1 = x1;
}

// ---------------- MUFU-free exp ----------------
__device__ __forceinline__ float fast_exp(float x) {
    float t = x * 1.4426950408889634f;
    float n = rintf(t);
    float g = (t - n) * 0.6931471805599453f;
    float p = 1.9841269841e-4f;
    p = fmaf(p, g, 1.3888888889e-3f);
    p = fmaf(p, g, 8.3333333333e-3f);
    p = fmaf(p, g, 4.1666666667e-2f);
    p = fmaf(p, g, 1.6666666667e-1f);
    p = fmaf(p, g, 0.5f);
    p = fmaf(p, g, 1.0f);
    p = fmaf(p, g, 1.0f);
    float s = __int_as_float((127 + (int)n) << 23);
    return p * s;
}

// ================= K1: mega prologue (scores f32x2 | hist | meanv | sel-init | base-init) =================
__global__ void __launch_bounds__(256) k_mega(const float* __restrict__ q,
                                              const float* __restrict__ k,
                                              const float* __restrict__ v,
                                              const float* __restrict__ bias) {
    __shared__ union {
        struct { float qt[64][68]; float kt[64][68]; } sc;   // transposed [d][row]
        uint32_t hist[L];
        float part[256];
    } sm;
    int bid = blockIdx.x;
    int tid = threadIdx.x;

    if (bid < 512) {
        int b  = bid >> 8;
        int i0 = ((bid >> 4) & 15) * 64, j0 = (bid & 15) * 64;
        for (int u = tid; u < 4096; u += 256) {
            int r = u >> 6, c = u & 63;
            sm.sc.qt[c][r] = q[((size_t)b * L + i0 + r) * D + c];
            sm.sc.kt[c][r] = k[((size_t)b * L + j0 + r) * D + c];
        }
        __syncthreads();
        int tx = tid & 15, ty = tid >> 4;
        // packed accumulators: acc2[r][0]=(c0,c1), acc2[r][1]=(c2,c3); 0ull == (0.f,0.f)
        unsigned long long acc2[4][2] = {};
#pragma unroll 8
        for (int d = 0; d < 64; d++) {
            float4 a4 = *(const float4*)&sm.sc.qt[d][ty * 4];
            unsigned long long b01 = *(const unsigned long long*)&sm.sc.kt[d][tx * 4];
            unsigned long long b23 = *(const unsigned long long*)&sm.sc.kt[d][tx * 4 + 2];
            unsigned long long ap;
            ap = bcast2(a4.x); ffma2(acc2[0][0], ap, b01); ffma2(acc2[0][1], ap, b23);
            ap = bcast2(a4.y); ffma2(acc2[1][0], ap, b01); ffma2(acc2[1][1], ap, b23);
            ap = bcast2(a4.z); ffma2(acc2[2][0], ap, b01); ffma2(acc2[2][1], ap, b23);
            ap = bcast2(a4.w); ffma2(acc2[3][0], ap, b01); ffma2(acc2[3][1], ap, b23);
        }
#pragma unroll
        for (int r = 0; r < 4; r++) {
            float2 lo = unpack2(acc2[r][0]);
            float2 hi = unpack2(acc2[r][1]);
            float4 o; o.x = lo.x; o.y = lo.y; o.z = hi.x; o.w = hi.y;
            *(float4*)&g_S[b][i0 + ty * 4 + r][j0 + tx * 4] = o;
        }
    } else if (bid < 544) {
        int t = bid - 512;
        int h = t & 15, b = t >> 4;
        for (int j = tid; j < L; j += 256) sm.hist[j] = 0;
        __syncthreads();
        uint32_t hk0, hk1, s0, s1;
        threefry2x32(0u, 42u, 0u, (uint32_t)h, hk0, hk1);
        threefry2x32(hk0, hk1, 0u, 1u, s0, s1);
        for (int i = tid; i < USAMP; i += 256) {
            uint32_t b1, b2;
            threefry2x32(s0, s1, 0u, (uint32_t)(b * USAMP + i), b1, b2);
            atomicAdd(&sm.hist[(b1 ^ b2) & 1023u], 1u);
        }
        __syncthreads();
        for (int j = tid; j < L; j += 256)
            g_cnt8[b][j][h] = (uint8_t)sm.hist[j];
    } else if (bid < 546) {
        int b = bid - 544;
        int d = tid & 63, g = tid >> 6;
        float s = 0.f;
        for (int kk = g; kk < L; kk += 4)
            s += v[((size_t)b * L + kk) * D + d];
        sm.part[tid] = s;
        __syncthreads();
        if (tid < 64)
            g_meanv[b][tid] = (sm.part[tid] + sm.part[tid + 64] + sm.part[tid + 128] + sm.part[tid + 192]) * (1.0f / 1024.0f);
    } else if (bid < 554) {
        int t = bid - 546;
        int base = (t * 256 + tid) * 16;
        int* sp = &g_sel[0][0][0];
#pragma unroll
        for (int e = 0; e < 16; e++) sp[base + e] = -1;
    } else {
        int b = bid - 554;
        int c4 = tid * 4;
        *(float4*)&g_base[b][c4] = *(const float4*)&bias[c4];
    }
}

// ================= K2: K-split base GEMV + fused measure (argmax-fallback masked max) =================
__global__ void __launch_bounds__(256) k_measure_base(const float* __restrict__ W) {
    int bid = blockIdx.x;
    int tid = threadIdx.x;
    if (bid < 32) {
        int b  = bid >> 4;
        int kc = (bid >> 2) & 3;
        int c  = (bid & 3) * 256 + tid;
        __shared__ float mv[64];
        if (tid < 64) mv[tid] = g_meanv[b][tid];
        __syncthreads();
        int k0 = kc * 256;
        float a0 = 0.f, a1 = 0.f, a2 = 0.f, a3 = 0.f, a4 = 0.f, a5 = 0.f, a6 = 0.f, a7 = 0.f;
        for (int k = k0; k < k0 + 256; k += 8) {
            a0 += mv[(k)     & 63] * W[(size_t)(k)     * DMODEL + c];
            a1 += mv[(k + 1) & 63] * W[(size_t)(k + 1) * DMODEL + c];
            a2 += mv[(k + 2) & 63] * W[(size_t)(k + 2) * DMODEL + c];
            a3 += mv[(k + 3) & 63] * W[(size_t)(k + 3) * DMODEL + c];
            a4 += mv[(k + 4) & 63] * W[(size_t)(k + 4) * DMODEL + c];
            a5 += mv[(k + 5) & 63] * W[(size_t)(k + 5) * DMODEL + c];
            a6 += mv[(k + 6) & 63] * W[(size_t)(k + 6) * DMODEL + c];
            a7 += mv[(k + 7) & 63] * W[(size_t)(k + 7) * DMODEL + c];
        }
        g_basep[kc][b][c] = ((a0 + a1) + (a2 + a3)) + ((a4 + a5) + (a6 + a7));
    } else {
        int mb = bid - 32;
        int wid = tid >> 5, lane = tid & 31;
        int rowg = mb * 8 + wid;
        int b = rowg >> 10, row = rowg & 1023;
        const float* Srow = g_S[b][row];

        float mx = -3.4e38f;
        int jmx = 0;
        float sv[16];
#pragma unroll
        for (int h = 0; h < 16; h++) sv[h] = 0.f;

        for (int j = lane; j < L; j += 32) {
            float s = Srow[j];
            uint4 c16 = *(const uint4*)&g_cnt8[b][j][0];
            if (s > mx) { mx = s; jmx = j; }
#define SP(wrd, base) { \
            sv[(base)]     += (float)((wrd) & 255u)         * s; \
            sv[(base) + 1] += (float)(((wrd) >> 8) & 255u)  * s; \
            sv[(base) + 2] += (float)(((wrd) >> 16) & 255u) * s; \
            sv[(base) + 3] += (float)((wrd) >> 24)          * s; }
            SP(c16.x, 0) SP(c16.y, 4) SP(c16.z, 8) SP(c16.w, 12)
#undef SP
        }

#pragma unroll
        for (int off = 16; off; off >>= 1) {
            float om = __shfl_xor_sync(0xffffffffu, mx, off);
            int   oj = __shfl_xor_sync(0xffffffffu, jmx, off);
            if (om > mx || (om == mx && oj < jmx)) { mx = om; jmx = oj; }
        }
#pragma unroll
        for (int h = 0; h < 16; h++) {
            float s = sv[h];
#pragma unroll
            for (int off = 16; off; off >>= 1)
                s += __shfl_down_sync(0xffffffffu, s, off);
            sv[h] = s;
        }

        uint4 cj = *(const uint4*)&g_cnt8[b][jmx][0];
        uint32_t em = 0;
        {
            uint32_t w0 = cj.x, w1 = cj.y, w2 = cj.z, w3 = cj.w;
#pragma unroll
            for (int t = 0; t < 4; t++) {
                if (((w0 >> (t * 8)) & 255u) == 0) em |= 1u << t;
                if (((w1 >> (t * 8)) & 255u) == 0) em |= 1u << (4 + t);
                if (((w2 >> (t * 8)) & 255u) == 0) em |= 1u << (8 + t);
                if (((w3 >> (t * 8)) & 255u) == 0) em |= 1u << (12 + t);
            }
        }

#pragma unroll
        for (int h = 0; h < 16; h++) {
            float mh = mx;
            if (em & (1u << h)) {
                float m2 = -3.4e38f;
                for (int j = lane; j < L; j += 32) {
                    float s = Srow[j];
                    if (g_cnt8[b][j][h]) m2 = fmaxf(m2, s);
                }
#pragma unroll
                for (int off = 16; off; off >>= 1)
                    m2 = fmaxf(m2, __shfl_xor_sync(0xffffffffu, m2, off));
                mh = m2;
            }
            if (lane == 0) g_M[b][h][row] = mh - sv[h] / 7097.0f;
        }
    }
}

// ================= K3: top-34 via radix-select =================
__global__ void __launch_bounds__(1024) k_topk() {
    int h = blockIdx.x, b = blockIdx.y;
    int tid = threadIdx.x;
    __shared__ uint32_t hist[64];
    __shared__ uint32_t s_digit;
    __shared__ int s_rank;
    __shared__ int s_cnt;

    float val = g_M[b][h][tid];
    uint32_t ub = __float_as_uint(val);
    uint32_t u = (ub & 0x80000000u) ? ~ub : (ub | 0x80000000u);
    unsigned long long key = ((unsigned long long)u << 10) | (unsigned long long)(1023 - tid);

    unsigned long long prefix = 0ull;
    int rank = USEL;
    if (tid == 0) s_cnt = 0;

#pragma unroll
    for (int shift = 36; shift >= 0; shift -= 6) {
        if (tid < 64) hist[tid] = 0;
        __syncthreads();
        if ((key >> (shift + 6)) == prefix)
            atomicAdd(&hist[(uint32_t)(key >> shift) & 63u], 1u);
        __syncthreads();
        if (tid == 0) {
            int c = 0;
            for (int d = 63; d >= 0; d--) {
                c += (int)hist[d];
                if (c >= rank) {
                    s_digit = (uint32_t)d;
                    s_rank = rank - (c - (int)hist[d]);
                    break;
                }
            }
        }
        __syncthreads();
        prefix = (prefix << 6) | (unsigned long long)s_digit;
        rank = s_rank;
        __syncthreads();
    }

    if (key >= prefix) {
        int slot = atomicAdd(&s_cnt, 1);
        g_top[b][h][slot] = tid;
        g_sel[b][h][tid] = slot;
    }
}

// ================= K4: PV partials — f32x2 dim-pairs =================
__global__ void __launch_bounds__(128) k_pv(const float* __restrict__ v) {
    __shared__ float vs[CHK][64];
    __shared__ float es[USEL][CHK];
    __shared__ int   tops[USEL];
    int ch = blockIdx.x, h = blockIdx.y, b = blockIdx.z;
    int k0 = ch * CHK;
    int tid = threadIdx.x;

    if (tid < USEL) tops[tid] = g_top[b][h][tid];
    for (int u = tid; u < CHK * 64 / 4; u += 128) {
        int kk = u >> 4, c4 = (u & 15) * 4;
        *(float4*)&vs[kk][c4] = *(const float4*)&v[((size_t)b * L + k0 + kk) * D + c4];
    }
    __syncthreads();

    for (int u = tid; u < USEL * CHK; u += 128) {
        int row = u >> 5, j = u & 31;
        es[row][j] = fast_exp(g_S[b][tops[row]][k0 + j] * 0.03125f);
    }
    __syncthreads();

    if (tid < USEL) {
        float s = 0.f;
#pragma unroll
        for (int j = 0; j < CHK; j++) s += es[tid][j];
        g_psum[b][h][tid][ch] = s;
    }

    int r  = tid >> 4;            // 0..7
    int d0 = (tid & 15) * 4;      // dim quad -> two packed pairs
    unsigned long long accp[5][2] = {};
    bool has5 = (r < 2);

#pragma unroll
    for (int kk = 0; kk < CHK; kk += 4) {
        unsigned long long w0a = *(const unsigned long long*)&vs[kk][d0];
        unsigned long long w0b = *(const unsigned long long*)&vs[kk][d0 + 2];
        unsigned long long w1a = *(const unsigned long long*)&vs[kk + 1][d0];
        unsigned long long w1b = *(const unsigned long long*)&vs[kk + 1][d0 + 2];
        unsigned long long w2a = *(const unsigned long long*)&vs[kk + 2][d0];
        unsigned long long w2b = *(const unsigned long long*)&vs[kk + 2][d0 + 2];
        unsigned long long w3a = *(const unsigned long long*)&vs[kk + 3][d0];
        unsigned long long w3b = *(const unsigned long long*)&vs[kk + 3][d0 + 2];
#pragma unroll
        for (int jj = 0; jj < 4; jj++) {
            float4 e = *(float4*)&es[r + jj * 8][kk];
            unsigned long long ep;
            ep = bcast2(e.x); ffma2(accp[jj][0], ep, w0a); ffma2(accp[jj][1], ep, w0b);
            ep = bcast2(e.y); ffma2(accp[jj][0], ep, w1a); ffma2(accp[jj][1], ep, w1b);
            ep = bcast2(e.z); ffma2(accp[jj][0], ep, w2a); ffma2(accp[jj][1], ep, w2b);
            ep = bcast2(e.w); ffma2(accp[jj][0], ep, w3a); ffma2(accp[jj][1], ep, w3b);
        }
        if (has5) {
            float4 e = *(float4*)&es[r + 32][kk];
            unsigned long long ep;
            ep = bcast2(e.x); ffma2(accp[4][0], ep, w0a); ffma2(accp[4][1], ep, w0b);
            ep = bcast2(e.y); ffma2(accp[4][0], ep, w1a); ffma2(accp[4][1], ep, w1b);
            ep = bcast2(e.z); ffma2(accp[4][0], ep, w2a); ffma2(accp[4][1], ep, w2b);
            ep = bcast2(e.w); ffma2(accp[4][0], ep, w3a); ffma2(accp[4][1], ep, w3b);
        }
    }
#pragma unroll
    for (int jj = 0; jj < 4; jj++) {
        float2 lo = unpack2(accp[jj][0]);
        float2 hi = unpack2(accp[jj][1]);
        float4 o; o.x = lo.x; o.y = lo.y; o.z = hi.x; o.w = hi.y;
        *(float4*)&g_pacc[b][h][r + jj * 8][ch][d0] = o;
    }
    if (has5) {
        float2 lo = unpack2(accp[4][0]);
        float2 hi = unpack2(accp[4][1]);
        float4 o; o.x = lo.x; o.y = lo.y; o.z = hi.x; o.w = hi.y;
        *(float4*)&g_pacc[b][h][r + 32][ch][d0] = o;
    }
}

// ================= K5: delta = pacc_sum/psum_sum - meanv (NCH=32) =================
__global__ void __launch_bounds__(64) k_delta() {
    int i = blockIdx.x, h = blockIdx.y, b = blockIdx.z;
    int tid = threadIdx.x;
    __shared__ float rsv;

    if (tid < 32) {
        float s = g_psum[b][h][i][tid];
#pragma unroll
        for (int off = 16; off; off >>= 1) s += __shfl_down_sync(0xffffffffu, s, off);
        if (tid == 0) rsv = 1.0f / s;
    }
    __syncthreads();

    float s = 0.f;
#pragma unroll
    for (int c = 0; c < NCH; c++) s += g_pacc[b][h][i][c][tid];
    g_delta[b][h][i][tid] = s * rsv - g_meanv[b][tid];
}

// ================= K6: correction GEMM =================
__global__ void __launch_bounds__(128) k_corr(const float* __restrict__ W) {
    __shared__ float sd[USEL][64];
    int nc = blockIdx.x;
    int h  = blockIdx.y, b = blockIdx.z;
    int tid = threadIdx.x;
    int n0 = nc * 128;

    for (int u = tid; u < USEL * 64 / 2; u += 128) {
        int row = u >> 5, c2 = (u & 31) * 2;
        *(float2*)&sd[row][c2] = *(const float2*)&g_delta[b][h][row][c2];
    }
    __syncthreads();

    float acc[USEL];
#pragma unroll
    for (int i = 0; i < USEL; i++) acc[i] = 0.f;

    const float* Wp = W + (size_t)(h * 64) * DMODEL + n0 + tid;
#pragma unroll 4
    for (int k = 0; k < 64; k++) {
        float w = Wp[(size_t)k * DMODEL];
#pragma unroll
        for (int i = 0; i < USEL; i++)
            acc[i] += sd[i][k] * w;
    }
#pragma unroll
    for (int i = 0; i < USEL; i++)
        g_E[b][h][i][n0 + tid] = acc[i];
}

// ================= K7: assemble output =================
__global__ void __launch_bounds__(256) k_out(float* __restrict__ out) {
    __shared__ int sel[16];
    int bid = blockIdx.x;
    int b = bid >> 10, qq = bid & 1023;
    int tid = threadIdx.x;
    if (tid < 16) sel[tid] = g_sel[b][tid][qq];
    __syncthreads();

    int c4 = tid * 4;
    float4 val = *(const float4*)&g_base[b][c4];
#pragma unroll
    for (int kc = 0; kc < 4; kc++) {
        float4 p = *(const float4*)&g_basep[kc][b][c4];
        val.x += p.x; val.y += p.y; val.z += p.z; val.w += p.w;
    }
#pragma unroll
    for (int h = 0; h < 16; h++) {
        int i = sel[h];
        if (i >= 0) {
            float4 e = *(const float4*)&g_E[b][h][i][c4];
            val.x += e.x; val.y += e.y; val.z += e.z; val.w += e.w;
        }
    }
    *(float4*)&out[(size_t)(b * L + qq) * DMODEL + c4] = val;
}

// ---------------- launch ----------------
extern "C" void kernel_launch(void* const* d_in, const int* in_sizes, int n_in,
                              void* d_out, int out_size) {
    const float* q    = (const float*)d_in[0];
    const float* k    = (const float*)d_in[1];
    const float* v    = (const float*)d_in[2];
    const float* W    = (const float*)d_in[3];
    const float* bias = (const float*)d_in[4];
    float* out = (float*)d_out;

    k_mega<<<556, 256>>>(q, k, v, bias);

    k_measure_base<<<288, 256>>>(W);

    dim3 gT(H_HEADS, BATCH);
    k_topk<<<gT, 1024>>>();

    dim3 gPV(NCH, H_HEADS, BATCH);
    k_pv<<<gPV, 128>>>(v);

    dim3 gD(USEL, H_HEADS, BATCH);
    k_delta<<<gD, 64>>>();

    dim3 gC(8, H_HEADS, BATCH);
    k_corr<<<gC, 128>>>(W);

    k_out<<<MROWS, 256>>>(out);
}